// round 4
// baseline (speedup 1.0000x reference)
#include <cuda_runtime.h>
#include <cuda_bf16.h>

// Problem constants (fixed by the reference).
static constexpr int Bn = 128;   // batch
static constexpr int Qn = 1000;  // queries
static constexpr int Cn = 256;   // classes
static constexpr int Tn = 300;   // targets
static constexpr int WARPS = 8;  // q-rows per block
static constexpr int NTHREADS = WARPS * 32;

// If labels were materialized as int64 (little-endian), every odd 32-bit word
// of the buffer is zero (labels in [0,256)). Probe 16 odd words.
__device__ __forceinline__ bool labels_are_i64(const int* __restrict__ p) {
    int acc = 0;
#pragma unroll
    for (int i = 0; i < 16; i++) acc |= p[2 * i + 1];
    return acc == 0;
}

__global__ __launch_bounds__(NTHREADS)
void hungarian_cost_kernel(const float* __restrict__ logits,
                           const float* __restrict__ pboxes,
                           const int*   __restrict__ labels_raw,
                           const float* __restrict__ tboxes,
                           float*       __restrict__ out) {
    __shared__ float4 s_tb[Tn];            // tgt boxes for this batch  (4.8 KB)
    __shared__ int    s_lab[Tn];           // labels                    (1.2 KB)
    __shared__ float  s_prob[WARPS][Cn];   // -softmax per q-row        (8 KB)

    const int b   = blockIdx.y;
    const int q0  = blockIdx.x * WARPS;
    const int tid = threadIdx.x;
    const int w   = tid >> 5;
    const int l   = tid & 31;
    const int q   = q0 + w;

    const bool is64 = labels_are_i64(labels_raw);

    // Stage target boxes + labels for batch b into smem (block-cooperative).
    {
        float* tbf = reinterpret_cast<float*>(s_tb);
        const float* src = tboxes + b * Tn * 4;
        for (int i = tid; i < Tn * 4; i += NTHREADS) tbf[i] = src[i];
        for (int i = tid; i < Tn; i += NTHREADS) {
            int idx = b * Tn + i;
            s_lab[i] = is64 ? labels_raw[2 * idx] : labels_raw[idx];
        }
    }

    // ---- Softmax over 256 classes for this warp's q-row (warp-local). ----
    const float* lg = logits + ((b * Qn) + q) * Cn;
    float v[8];
    float mx = -1e30f;
#pragma unroll
    for (int i = 0; i < 8; i++) {
        v[i] = lg[i * 32 + l];
        mx = fmaxf(mx, v[i]);
    }
#pragma unroll
    for (int o = 16; o; o >>= 1) mx = fmaxf(mx, __shfl_xor_sync(0xffffffffu, mx, o));
    float s = 0.0f;
#pragma unroll
    for (int i = 0; i < 8; i++) {
        v[i] = __expf(v[i] - mx);
        s += v[i];
    }
#pragma unroll
    for (int o = 16; o; o >>= 1) s += __shfl_xor_sync(0xffffffffu, s, o);
    const float ninv = -1.0f / s;
#pragma unroll
    for (int i = 0; i < 8; i++) s_prob[w][i * 32 + l] = v[i] * ninv;

    // Pred box for this q-row (same 16B load in all lanes -> L1 broadcast).
    const float4 pb = *reinterpret_cast<const float4*>(pboxes + ((b * Qn) + q) * 4);

    __syncthreads();  // s_tb / s_lab ready (s_prob is warp-private)

    // ---- Emit 300 outputs for this q-row, coalesced. ----
    float* orow = out + ((b * Qn) + q) * Tn;
    const float* pw = s_prob[w];
#pragma unroll 2
    for (int t = l; t < Tn; t += 32) {
        const float4 tb = s_tb[t];
        float cb = fabsf(pb.x - tb.x) + fabsf(pb.y - tb.y) +
                   fabsf(pb.z - tb.z) + fabsf(pb.w - tb.w);
        orow[t] = cb + pw[s_lab[t]];
    }
}

extern "C" void kernel_launch(void* const* d_in, const int* in_sizes, int n_in,
                              void* d_out, int out_size) {
    const float* logits = (const float*)d_in[0];
    const float* pboxes = (const float*)d_in[1];
    const int*   labels = (const int*)d_in[2];
    const float* tboxes = (const float*)d_in[3];
    float* out = (float*)d_out;

    dim3 grid(Qn / WARPS, Bn);  // 125 x 128
    hungarian_cost_kernel<<<grid, NTHREADS>>>(logits, pboxes, labels, tboxes, out);
}

// round 5
// speedup vs baseline: 1.2746x; 1.2746x over previous
#include <cuda_runtime.h>
#include <cuda_bf16.h>

// Problem constants (fixed by the reference).
static constexpr int Bn = 128;   // batch
static constexpr int Qn = 1000;  // queries
static constexpr int Cn = 256;   // classes
static constexpr int Tn = 300;   // targets

static constexpr int W  = 4;     // warps per block
static constexpr int R  = 10;    // q-rows per warp
static constexpr int ROWS = W * R;     // 40 rows per block (1000/40 = 25 blocks)
static constexpr int NT = W * 32;      // 128 threads
static constexpr int KT = 10;          // ceil(Tn/32): t-slots per lane

// If labels were materialized as int64 (little-endian), every odd 32-bit word
// of the buffer is zero (labels in [0,256)). Probe 16 odd words.
__device__ __forceinline__ bool labels_are_i64(const int* __restrict__ p) {
    int acc = 0;
#pragma unroll
    for (int i = 0; i < 16; i++) acc |= p[2 * i + 1];
    return acc == 0;
}

__global__ __launch_bounds__(NT)
void hungarian_cost_kernel(const float* __restrict__ logits,
                           const float* __restrict__ pboxes,
                           const int*   __restrict__ labels_raw,
                           const float* __restrict__ tboxes,
                           float*       __restrict__ out) {
    __shared__ float s_prob[W][Cn];   // -softmax for each warp's current row (4 KB)

    const int b   = blockIdx.y;
    const int tid = threadIdx.x;
    const int w   = tid >> 5;
    const int l   = tid & 31;

    const bool is64 = labels_are_i64(labels_raw);

    // ---- Preload this lane's fixed t-set (boxes + labels) into registers. ----
    // Lane l owns t = l, l+32, ..., l+288. Loaded ONCE, reused for R rows.
    float4 tb[KT];
    int    lab[KT];
    const float4* tbp = reinterpret_cast<const float4*>(tboxes) + b * Tn;
#pragma unroll
    for (int k = 0; k < KT; k++) {
        const int t = l + 32 * k;
        if (t < Tn) {
            tb[k]  = tbp[t];
            const int idx = b * Tn + t;
            lab[k] = is64 ? labels_raw[2 * idx] : labels_raw[idx];
        } else {
            tb[k]  = make_float4(0.f, 0.f, 0.f, 0.f);
            lab[k] = 0;
        }
    }

    const int q0 = blockIdx.x * ROWS + w * R;

    for (int r = 0; r < R; r++) {
        const int q = q0 + r;

        // ---- Softmax over 256 classes (warp-local, vectorized loads). ----
        // Lane l holds classes [4l..4l+3] and [128+4l..128+4l+3].
        const float4* lg4 = reinterpret_cast<const float4*>(
            logits + ((size_t)(b * Qn) + q) * Cn);
        float4 u0 = lg4[l];
        float4 u1 = lg4[l + 32];

        float mx = fmaxf(fmaxf(fmaxf(u0.x, u0.y), fmaxf(u0.z, u0.w)),
                         fmaxf(fmaxf(u1.x, u1.y), fmaxf(u1.z, u1.w)));
#pragma unroll
        for (int o = 16; o; o >>= 1) mx = fmaxf(mx, __shfl_xor_sync(0xffffffffu, mx, o));

        u0.x = __expf(u0.x - mx); u0.y = __expf(u0.y - mx);
        u0.z = __expf(u0.z - mx); u0.w = __expf(u0.w - mx);
        u1.x = __expf(u1.x - mx); u1.y = __expf(u1.y - mx);
        u1.z = __expf(u1.z - mx); u1.w = __expf(u1.w - mx);

        float s = (u0.x + u0.y) + (u0.z + u0.w) + (u1.x + u1.y) + (u1.z + u1.w);
#pragma unroll
        for (int o = 16; o; o >>= 1) s += __shfl_xor_sync(0xffffffffu, s, o);
        const float ninv = -1.0f / s;

        float4* pw4 = reinterpret_cast<float4*>(s_prob[w]);
        pw4[l]      = make_float4(u0.x * ninv, u0.y * ninv, u0.z * ninv, u0.w * ninv);
        pw4[l + 32] = make_float4(u1.x * ninv, u1.y * ninv, u1.z * ninv, u1.w * ninv);
        __syncwarp();   // prob table visible within the warp

        // Pred box (same 16B for whole warp -> L1 broadcast).
        const float4 pb = reinterpret_cast<const float4*>(pboxes)[b * Qn + q];

        float* orow = out + ((size_t)(b * Qn) + q) * Tn;
        const float* pw = s_prob[w];
#pragma unroll
        for (int k = 0; k < KT; k++) {
            const int t = l + 32 * k;
            if (t < Tn) {
                float cb = fabsf(pb.x - tb[k].x) + fabsf(pb.y - tb[k].y) +
                           fabsf(pb.z - tb[k].z) + fabsf(pb.w - tb[k].w);
                orow[t] = cb + pw[lab[k]];
            }
        }
        __syncwarp();   // done reading prob table before next row overwrites it
    }
}

extern "C" void kernel_launch(void* const* d_in, const int* in_sizes, int n_in,
                              void* d_out, int out_size) {
    const float* logits = (const float*)d_in[0];
    const float* pboxes = (const float*)d_in[1];
    const int*   labels = (const int*)d_in[2];
    const float* tboxes = (const float*)d_in[3];
    float* out = (float*)d_out;

    dim3 grid(Qn / ROWS, Bn);  // 25 x 128
    hungarian_cost_kernel<<<grid, NT>>>(logits, pboxes, labels, tboxes, out);
}

// round 6
// speedup vs baseline: 1.3424x; 1.0532x over previous
#include <cuda_runtime.h>
#include <cuda_bf16.h>

// Problem constants (fixed by the reference).
static constexpr int Bn = 128;   // batch
static constexpr int Qn = 1000;  // queries
static constexpr int Cn = 256;   // classes
static constexpr int Tn = 300;   // targets

static constexpr int W  = 4;     // warps per block
static constexpr int R  = 10;    // q-rows per warp
static constexpr int ROWS = W * R;     // 40 rows per block (1000/40 = 25 blocks)
static constexpr int NT = W * 32;      // 128 threads
static constexpr int KT = 10;          // ceil(Tn/32): t-slots per lane

// If labels were materialized as int64 (little-endian), every odd 32-bit word
// of the buffer is zero (labels in [0,256)). Probe 16 odd words.
__device__ __forceinline__ bool labels_are_i64(const int* __restrict__ p) {
    int acc = 0;
#pragma unroll
    for (int i = 0; i < 16; i++) acc |= p[2 * i + 1];
    return acc == 0;
}

__global__ __launch_bounds__(NT, 6)
void hungarian_cost_kernel(const float* __restrict__ logits,
                           const float* __restrict__ pboxes,
                           const int*   __restrict__ labels_raw,
                           const float* __restrict__ tboxes,
                           float*       __restrict__ out) {
    // Double-buffered per-warp prob tables: gather of row r overlaps with
    // softmax stores of row r+1 (no trailing syncwarp needed).
    __shared__ float s_prob[2][W][Cn];   // 8 KB

    const int b   = blockIdx.y;
    const int tid = threadIdx.x;
    const int w   = tid >> 5;
    const int l   = tid & 31;

    const bool is64 = labels_are_i64(labels_raw);

    // ---- Preload this lane's fixed t-set (boxes + labels) into registers. ----
    float4 tb[KT];
    int    lab[KT];
    const float4* tbp = reinterpret_cast<const float4*>(tboxes) + b * Tn;
#pragma unroll
    for (int k = 0; k < KT; k++) {
        const int t = l + 32 * k;
        if (t < Tn) {
            tb[k]  = tbp[t];
            const int idx = b * Tn + t;
            lab[k] = is64 ? labels_raw[2 * idx] : labels_raw[idx];
        } else {
            tb[k]  = make_float4(0.f, 0.f, 0.f, 0.f);
            lab[k] = 0;
        }
    }

    const int q0 = blockIdx.x * ROWS + w * R;
    const float4* lgbase = reinterpret_cast<const float4*>(logits) + (size_t)(b * Qn) * (Cn / 4);

    // Prime the pipeline: logits + pred box for row 0.
    float4 u0 = lgbase[(size_t)q0 * 64 + l];
    float4 u1 = lgbase[(size_t)q0 * 64 + l + 32];
    float4 pb = reinterpret_cast<const float4*>(pboxes)[b * Qn + q0];

    int buf = 0;
#pragma unroll 2
    for (int r = 0; r < R; r++) {
        const int q = q0 + r;

        // ---- Prefetch next row's logits + pbox BEFORE any compute on row r. ----
        float4 n0, n1, npb;
        const int qn = (r + 1 < R) ? (q + 1) : q;   // clamp: harmless dup load
        n0  = lgbase[(size_t)qn * 64 + l];
        n1  = lgbase[(size_t)qn * 64 + l + 32];
        npb = reinterpret_cast<const float4*>(pboxes)[b * Qn + qn];

        // ---- Softmax over 256 classes (warp-local). ----
        float mx = fmaxf(fmaxf(fmaxf(u0.x, u0.y), fmaxf(u0.z, u0.w)),
                         fmaxf(fmaxf(u1.x, u1.y), fmaxf(u1.z, u1.w)));
#pragma unroll
        for (int o = 16; o; o >>= 1) mx = fmaxf(mx, __shfl_xor_sync(0xffffffffu, mx, o));

        u0.x = __expf(u0.x - mx); u0.y = __expf(u0.y - mx);
        u0.z = __expf(u0.z - mx); u0.w = __expf(u0.w - mx);
        u1.x = __expf(u1.x - mx); u1.y = __expf(u1.y - mx);
        u1.z = __expf(u1.z - mx); u1.w = __expf(u1.w - mx);

        float s = (u0.x + u0.y) + (u0.z + u0.w) + (u1.x + u1.y) + (u1.z + u1.w);
#pragma unroll
        for (int o = 16; o; o >>= 1) s += __shfl_xor_sync(0xffffffffu, s, o);
        const float ninv = -1.0f / s;

        float4* pw4 = reinterpret_cast<float4*>(s_prob[buf][w]);
        pw4[l]      = make_float4(u0.x * ninv, u0.y * ninv, u0.z * ninv, u0.w * ninv);
        pw4[l + 32] = make_float4(u1.x * ninv, u1.y * ninv, u1.z * ninv, u1.w * ninv);
        __syncwarp();   // STS visible to warp before gather

        // ---- Emit 300 outputs for this q-row (coalesced within the lane set). ----
        float* orow = out + ((size_t)(b * Qn) + q) * Tn;
        const float* pw = s_prob[buf][w];
#pragma unroll
        for (int k = 0; k < KT; k++) {
            const int t = l + 32 * k;
            if (t < Tn) {
                float cb = fabsf(pb.x - tb[k].x) + fabsf(pb.y - tb[k].y) +
                           fabsf(pb.z - tb[k].z) + fabsf(pb.w - tb[k].w);
                orow[t] = cb + pw[lab[k]];
            }
        }

        // Rotate pipeline registers / buffer (no syncwarp: next STS hits other buf).
        u0 = n0; u1 = n1; pb = npb;
        buf ^= 1;
    }
}

extern "C" void kernel_launch(void* const* d_in, const int* in_sizes, int n_in,
                              void* d_out, int out_size) {
    const float* logits = (const float*)d_in[0];
    const float* pboxes = (const float*)d_in[1];
    const int*   labels = (const int*)d_in[2];
    const float* tboxes = (const float*)d_in[3];
    float* out = (float*)d_out;

    dim3 grid(Qn / ROWS, Bn);  // 25 x 128
    hungarian_cost_kernel<<<grid, NT>>>(logits, pboxes, labels, tboxes, out);
}